// round 15
// baseline (speedup 1.0000x reference)
#include <cuda_runtime.h>
#include <cuda_bf16.h>

#define NMAX 10
#define LP1  8
#define NZ   80
#define THR  0.0625f
#define CAP  (1u << 21)

__device__ unsigned int g_ctr  = 0;
__device__ unsigned int g_done = 0;
__device__ unsigned int g_list[CAP];   // packed (i << 4) | n

// ---------- K1: round-8 pristine fast kernel (measured 140 us). ----------
__global__ void __launch_bounds__(320, 6)
rb_fast_kernel(const float* __restrict__ r,
               const float* __restrict__ zeros,   // [NMAX, LP1]
               float* __restrict__ out,           // [N, LP1, NMAX]
               int nEdges)
{
    const int tid = threadIdx.x;            // 320 = 32 edges * 10 n
    const int i   = blockIdx.x * 32 + tid / NMAX;
    if (i >= nEdges) return;
    const int n   = tid - (tid / NMAX) * NMAX;

    const float rv   = __ldg(&r[i]);
    const float rv02 = rv * 0.2f;
    const float4 za = __ldg((const float4*)(zeros + n * LP1));
    const float4 zb = __ldg((const float4*)(zeros + n * LP1) + 1);
    const float z[8] = {za.x, za.y, za.z, za.w, zb.x, zb.y, zb.z, zb.w};

    float* o = out + (size_t)i * NZ + n;

    #pragma unroll
    for (int l = 0; l < LP1; ++l) {
        const float x = z[l] * rv02;
        float s, c, u;
        asm("sin.approx.f32 %0, %1;" : "=f"(s) : "f"(x));
        asm("cos.approx.f32 %0, %1;" : "=f"(c) : "f"(x));
        asm("rcp.approx.f32 %0, %1;" : "=f"(u) : "f"(x));
        float jm1 = s * u;                       // j0
        float v = jm1;
        if (l >= 1) {
            float j = fmaf(jm1, u, -(c * u));    // j1
            #pragma unroll
            for (int k = 2; k <= l; ++k) {
                float jn = fmaf((float)(2 * k - 1) * u, j, -jm1);
                jm1 = j; j = jn;
            }
            v = j;
        }
        o[l * NMAX] = v;
    }
}

// ---------- K1b: loop-free gate, thread = (i, n) ----------
__global__ void __launch_bounds__(320)
rb_gate_kernel(const float* __restrict__ r,
               const float* __restrict__ zeros,
               int nEdges)
{
    const int t = blockIdx.x * 320 + threadIdx.x;
    const int i = t / NMAX;
    const int n = t - i * NMAX;
    const bool live = (i < nEdges);

    const float rv = live ? __ldg(&r[i]) : 1.0e9f;
    const float z0 = __ldg(&zeros[n * LP1]);        // z[n][l=0], min over l
    const float x0 = __fmul_rn(__fmul_rn(z0, rv), 0.2f);

    if (live && x0 < THR) {
        const unsigned mask   = __activemask();
        const int      lane   = threadIdx.x & 31;
        const int      leader = __ffs(mask) - 1;
        const int      prefix = __popc(mask & ((1u << lane) - 1));
        unsigned base = 0;
        if (lane == leader) base = atomicAdd(&g_ctr, (unsigned)__popc(mask));
        base = __shfl_sync(mask, base, leader);
        const unsigned slot = base + prefix;
        if (slot < CAP)
            g_list[slot] = ((unsigned)i << 4) | (unsigned)n;
    }
}

// ---------- exact path (bit-validated rounds 4-14) ----------
__device__ __noinline__ float jl_exact(int l, float x)
{
    const double xd = (double)x;
    const double x2 = xd * xd;
    double sp = fma(x2,  1.0/6227020800.0, -1.0/39916800.0);
    sp = fma(x2, sp,  1.0/362880.0);
    sp = fma(x2, sp, -1.0/5040.0);
    sp = fma(x2, sp,  1.0/120.0);
    sp = fma(x2, sp, -1.0/6.0);
    const float s = __double2float_rn(fma(xd * x2, sp, xd));
    double cp = fma(x2, -1.0/87178291200.0, 1.0/479001600.0);
    cp = fma(x2, cp, -1.0/3628800.0);
    cp = fma(x2, cp,  1.0/40320.0);
    cp = fma(x2, cp, -1.0/720.0);
    cp = fma(x2, cp,  1.0/24.0);
    cp = fma(x2, cp, -0.5);
    const float c = __double2float_rn(fma(x2, cp, 1.0));

    float jm1 = __fdiv_rn(s, x);                                   // j0
    if (l == 0) return jm1;
    const float xx = __fmul_rn(x, x);
    float j = __fsub_rn(__fdiv_rn(s, xx), __fdiv_rn(c, x));        // j1
    #pragma unroll
    for (int k = 2; k <= 7; ++k) {
        if (k > l) break;
        float jn = __fsub_rn(__fmul_rn(__fdiv_rn((float)(2 * k - 1), x), j), jm1);
        jm1 = j; j = jn;
    }
    return j;
}

// ---------- K2: parallel fixup (~1 exact eval/thread) + counter self-reset ----------
__global__ void __launch_bounds__(256)
rb_fixup_kernel(const float* __restrict__ r,
                const float* __restrict__ zeros,
                float* __restrict__ out)
{
    const unsigned count  = min(g_ctr, CAP);
    const unsigned items  = count * LP1;
    const unsigned stride = gridDim.x * blockDim.x;

    for (unsigned j = blockIdx.x * blockDim.x + threadIdx.x; j < items; j += stride) {
        const unsigned p = g_list[j >> 3];
        const int l = (int)(j & 7u);
        const int i = (int)(p >> 4);
        const int n = (int)(p & 15u);
        const float rv = __ldg(&r[i]);
        const float z  = __ldg(&zeros[n * LP1 + l]);
        const float x  = __fmul_rn(__fmul_rn(z, rv), 0.2f);
        if (x < THR)
            out[(size_t)i * NZ + l * NMAX + n] = jl_exact(l, x);
    }

    // last block to finish resets counters for the next (graph-replayed) launch
    __syncthreads();
    if (threadIdx.x == 0) {
        const unsigned old = atomicAdd(&g_done, 1u);
        if (old == gridDim.x - 1u) {
            g_ctr  = 0u;
            g_done = 0u;
        }
    }
}

extern "C" void kernel_launch(void* const* d_in, const int* in_sizes, int n_in,
                              void* d_out, int out_size)
{
    const float* r     = (const float*)d_in[0];
    const float* zeros = (const float*)d_in[1];
    float* out         = (float*)d_out;
    const int n = in_sizes[0];

    rb_fast_kernel <<<(n + 31) / 32, 320>>>(r, zeros, out, n);
    rb_gate_kernel <<<(n * NMAX + 319) / 320, 320>>>(r, zeros, n);
    rb_fixup_kernel<<<3700, 256>>>(r, zeros, out);
}

// round 16
// speedup vs baseline: 1.2959x; 1.2959x over previous
#include <cuda_runtime.h>
#include <cuda_bf16.h>

#define NMAX 10
#define LP1  8
#define NZ   80
#define THR  0.0625f
#define CAP  (1u << 21)

__device__ unsigned int g_ctr  = 0;
__device__ unsigned int g_done = 0;
__device__ unsigned int g_list[CAP];   // packed (i << 4) | n

// ---------- K1: round-12 fast kernel + in-register compaction (hoisted) ----------
__global__ void __launch_bounds__(320, 6)
rb_fast_kernel(const float* __restrict__ r,
               const float* __restrict__ zeros,   // [NMAX, LP1]
               float* __restrict__ out,           // [N, LP1, NMAX]
               int nEdges)
{
    const int tid = threadIdx.x;            // 320 = 32 edges * 10 n
    const int i   = blockIdx.x * 32 + tid / NMAX;
    if (i >= nEdges) return;
    const int n   = tid - (tid / NMAX) * NMAX;

    const float rv   = __ldg(&r[i]);
    const float rv02 = rv * 0.2f;
    const float4 za = __ldg((const float4*)(zeros + n * LP1));
    const float4 zb = __ldg((const float4*)(zeros + n * LP1) + 1);
    const float z[8] = {za.x, za.y, za.z, za.w, zb.x, zb.y, zb.z, zb.w};

    // compaction first: exact-bit gate on l=0 (minimal x for this (i,n));
    // bookkeeping registers die before the recurrence loop begins.
    const float x0e = __fmul_rn(__fmul_rn(z[0], rv), 0.2f);
    if (x0e < THR) {
        const unsigned mask   = __activemask();
        const int      lane   = tid & 31;
        const int      leader = __ffs(mask) - 1;
        const int      prefix = __popc(mask & ((1u << lane) - 1));
        unsigned base = 0;
        if (lane == leader) base = atomicAdd(&g_ctr, (unsigned)__popc(mask));
        base = __shfl_sync(mask, base, leader);
        const unsigned slot = base + prefix;
        if (slot < CAP)
            g_list[slot] = ((unsigned)i << 4) | (unsigned)n;
    }

    float* o = out + (size_t)i * NZ + n;

    #pragma unroll
    for (int l = 0; l < LP1; ++l) {
        const float x = z[l] * rv02;
        float s, c, u;
        asm("sin.approx.f32 %0, %1;" : "=f"(s) : "f"(x));
        asm("cos.approx.f32 %0, %1;" : "=f"(c) : "f"(x));
        asm("rcp.approx.f32 %0, %1;" : "=f"(u) : "f"(x));
        float jm1 = s * u;                       // j0
        float v = jm1;
        if (l >= 1) {
            float j = fmaf(jm1, u, -(c * u));    // j1
            #pragma unroll
            for (int k = 2; k <= l; ++k) {
                float jn = fmaf((float)(2 * k - 1) * u, j, -jm1);
                jm1 = j; j = jn;
            }
            v = j;
        }
        o[l * NMAX] = v;
    }
}

// ---------- exact path (bit-validated rounds 4-15) ----------
__device__ __noinline__ float jl_exact(int l, float x)
{
    const double xd = (double)x;
    const double x2 = xd * xd;
    double sp = fma(x2,  1.0/6227020800.0, -1.0/39916800.0);
    sp = fma(x2, sp,  1.0/362880.0);
    sp = fma(x2, sp, -1.0/5040.0);
    sp = fma(x2, sp,  1.0/120.0);
    sp = fma(x2, sp, -1.0/6.0);
    const float s = __double2float_rn(fma(xd * x2, sp, xd));
    double cp = fma(x2, -1.0/87178291200.0, 1.0/479001600.0);
    cp = fma(x2, cp, -1.0/3628800.0);
    cp = fma(x2, cp,  1.0/40320.0);
    cp = fma(x2, cp, -1.0/720.0);
    cp = fma(x2, cp,  1.0/24.0);
    cp = fma(x2, cp, -0.5);
    const float c = __double2float_rn(fma(x2, cp, 1.0));

    float jm1 = __fdiv_rn(s, x);                                   // j0
    if (l == 0) return jm1;
    const float xx = __fmul_rn(x, x);
    float j = __fsub_rn(__fdiv_rn(s, xx), __fdiv_rn(c, x));        // j1
    #pragma unroll
    for (int k = 2; k <= 7; ++k) {
        if (k > l) break;
        float jn = __fsub_rn(__fmul_rn(__fdiv_rn((float)(2 * k - 1), x), j), jm1);
        jm1 = j; j = jn;
    }
    return j;
}

// ---------- K2: parallel fixup (~1 exact eval/thread) + counter self-reset ----------
__global__ void __launch_bounds__(256)
rb_fixup_kernel(const float* __restrict__ r,
                const float* __restrict__ zeros,
                float* __restrict__ out)
{
    const unsigned count  = min(g_ctr, CAP);
    const unsigned items  = count * LP1;
    const unsigned stride = gridDim.x * blockDim.x;

    for (unsigned j = blockIdx.x * blockDim.x + threadIdx.x; j < items; j += stride) {
        const unsigned p = g_list[j >> 3];
        const int l = (int)(j & 7u);
        const int i = (int)(p >> 4);
        const int n = (int)(p & 15u);
        const float rv = __ldg(&r[i]);
        const float z  = __ldg(&zeros[n * LP1 + l]);
        const float x  = __fmul_rn(__fmul_rn(z, rv), 0.2f);
        if (x < THR)
            out[(size_t)i * NZ + l * NMAX + n] = jl_exact(l, x);
    }

    // last block to finish resets counters for the next (graph-replayed) launch.
    // Every block has already read g_ctr above before incrementing g_done,
    // so the reset can never race a reader within this launch.
    __syncthreads();
    if (threadIdx.x == 0) {
        const unsigned old = atomicAdd(&g_done, 1u);
        if (old == gridDim.x - 1u) {
            g_ctr  = 0u;
            g_done = 0u;
        }
    }
}

extern "C" void kernel_launch(void* const* d_in, const int* in_sizes, int n_in,
                              void* d_out, int out_size)
{
    const float* r     = (const float*)d_in[0];
    const float* zeros = (const float*)d_in[1];
    float* out         = (float*)d_out;
    const int n = in_sizes[0];

    rb_fast_kernel <<<(n + 31) / 32, 320>>>(r, zeros, out, n);
    rb_fixup_kernel<<<3700, 256>>>(r, zeros, out);
}

// round 17
// speedup vs baseline: 1.3010x; 1.0040x over previous
#include <cuda_runtime.h>
#include <cuda_bf16.h>

#define NMAX 10
#define LP1  8
#define NZ   80
#define THR  0.0625f
#define CAP  (1u << 21)

__device__ unsigned int g_ctr  = 0;
__device__ unsigned int g_done = 0;
__device__ unsigned int g_list[CAP];   // packed (i << 4) | n

// ---------- K1: round-16 fast kernel + hoisted in-register compaction ----------
__global__ void __launch_bounds__(320, 6)
rb_fast_kernel(const float* __restrict__ r,
               const float* __restrict__ zeros,   // [NMAX, LP1]
               float* __restrict__ out,           // [N, LP1, NMAX]
               int nEdges)
{
    const int tid = threadIdx.x;            // 320 = 32 edges * 10 n
    const int i   = blockIdx.x * 32 + tid / NMAX;
    if (i >= nEdges) return;
    const int n   = tid - (tid / NMAX) * NMAX;

    const float rv   = __ldg(&r[i]);
    const float rv02 = rv * 0.2f;
    const float4 za = __ldg((const float4*)(zeros + n * LP1));
    const float4 zb = __ldg((const float4*)(zeros + n * LP1) + 1);
    const float z[8] = {za.x, za.y, za.z, za.w, zb.x, zb.y, zb.z, zb.w};

    // compaction: exact-bit gate on l=0 (minimal x for this (i,n))
    const float x0e = __fmul_rn(__fmul_rn(z[0], rv), 0.2f);
    if (x0e < THR) {
        const unsigned mask   = __activemask();
        const int      lane   = tid & 31;
        const int      leader = __ffs(mask) - 1;
        const int      prefix = __popc(mask & ((1u << lane) - 1));
        unsigned base = 0;
        if (lane == leader) base = atomicAdd(&g_ctr, (unsigned)__popc(mask));
        base = __shfl_sync(mask, base, leader);
        const unsigned slot = base + prefix;
        if (slot < CAP)
            g_list[slot] = ((unsigned)i << 4) | (unsigned)n;
    }

    float* o = out + (size_t)i * NZ + n;

    #pragma unroll
    for (int l = 0; l < LP1; ++l) {
        const float x = z[l] * rv02;
        float s, c, u;
        asm("sin.approx.f32 %0, %1;" : "=f"(s) : "f"(x));
        asm("cos.approx.f32 %0, %1;" : "=f"(c) : "f"(x));
        asm("rcp.approx.f32 %0, %1;" : "=f"(u) : "f"(x));
        float jm1 = s * u;                       // j0
        float v = jm1;
        if (l >= 1) {
            float j = fmaf(jm1, u, -(c * u));    // j1
            #pragma unroll
            for (int k = 2; k <= l; ++k) {
                float jn = fmaf((float)(2 * k - 1) * u, j, -jm1);
                jm1 = j; j = jn;
            }
            v = j;
        }
        o[l * NMAX] = v;
    }
}

// ---------- exact path: same IEEE ops, divisions hoisted for ILP ----------
__device__ __forceinline__ float jl_exact(int l, float x)
{
    const double xd = (double)x;
    const double x2 = xd * xd;
    double sp = fma(x2,  1.0/6227020800.0, -1.0/39916800.0);
    sp = fma(x2, sp,  1.0/362880.0);
    sp = fma(x2, sp, -1.0/5040.0);
    sp = fma(x2, sp,  1.0/120.0);
    sp = fma(x2, sp, -1.0/6.0);
    const float s = __double2float_rn(fma(xd * x2, sp, xd));
    double cp = fma(x2, -1.0/87178291200.0, 1.0/479001600.0);
    cp = fma(x2, cp, -1.0/3628800.0);
    cp = fma(x2, cp,  1.0/40320.0);
    cp = fma(x2, cp, -1.0/720.0);
    cp = fma(x2, cp,  1.0/24.0);
    cp = fma(x2, cp, -0.5);
    const float c = __double2float_rn(fma(x2, cp, 1.0));

    // all divisions are mutually independent: issue in parallel
    const float xx    = __fmul_rn(x, x);
    const float d_sx  = __fdiv_rn(s, x);
    const float d_sxx = __fdiv_rn(s, xx);
    const float d_cx  = __fdiv_rn(c, x);
    const float q[6]  = { __fdiv_rn( 3.0f, x), __fdiv_rn( 5.0f, x),
                          __fdiv_rn( 7.0f, x), __fdiv_rn( 9.0f, x),
                          __fdiv_rn(11.0f, x), __fdiv_rn(13.0f, x) };

    float jm1 = d_sx;                                   // j0
    if (l == 0) return jm1;
    float j = __fsub_rn(d_sxx, d_cx);                   // j1
    #pragma unroll
    for (int k = 2; k <= 7; ++k) {
        if (k > l) break;
        const float jn = __fsub_rn(__fmul_rn(q[k - 2], j), jm1);
        jm1 = j; j = jn;
    }
    return j;
}

// ---------- K2: fixup, warp-uniform l, ~1 exact eval/thread, self-reset ----------
__global__ void __launch_bounds__(256)
rb_fixup_kernel(const float* __restrict__ r,
                const float* __restrict__ zeros,
                float* __restrict__ out)
{
    const unsigned count  = min(g_ctr, CAP);
    const unsigned items  = count * LP1;
    const unsigned stride = gridDim.x * blockDim.x;

    for (unsigned j = blockIdx.x * blockDim.x + threadIdx.x; j < items; j += stride) {
        const unsigned l    = j / count;          // warp-uniform (count >> 32)
        const unsigned pair = j - l * count;      // consecutive -> coalesced
        const unsigned p = g_list[pair];
        const int i = (int)(p >> 4);
        const int n = (int)(p & 15u);
        const float rv = __ldg(&r[i]);
        const float z  = __ldg(&zeros[n * LP1 + l]);
        const float x  = __fmul_rn(__fmul_rn(z, rv), 0.2f);
        if (x < THR)
            out[(size_t)i * NZ + l * NMAX + n] = jl_exact((int)l, x);
    }

    // last block to finish resets counters for the next (graph-replayed) launch.
    __syncthreads();
    if (threadIdx.x == 0) {
        const unsigned old = atomicAdd(&g_done, 1u);
        if (old == gridDim.x - 1u) {
            g_ctr  = 0u;
            g_done = 0u;
        }
    }
}

extern "C" void kernel_launch(void* const* d_in, const int* in_sizes, int n_in,
                              void* d_out, int out_size)
{
    const float* r     = (const float*)d_in[0];
    const float* zeros = (const float*)d_in[1];
    float* out         = (float*)d_out;
    const int n = in_sizes[0];

    rb_fast_kernel <<<(n + 31) / 32, 320>>>(r, zeros, out, n);
    rb_fixup_kernel<<<3700, 256>>>(r, zeros, out);
}